// round 1
// baseline (speedup 1.0000x reference)
#include <cuda_runtime.h>
#include <cuda_bf16.h>
#include <cstdint>

#define NN 20000
#define P_PATH 512
#define S_SUB 64
#define DHID 256

// ---------------- scratch (static device globals; no allocation) ----------------
static __device__ float g_agg[NN * 128];
static __device__ float g_h1[NN * 24];
static __device__ float g_h2[NN * 64];
static __device__ float g_h3[NN * 128];
static __device__ float g_h4[NN * 256];
static __device__ float g_x[P_PATH * S_SUB * DHID];
static __device__ float g_q0[3 * 256];
static __device__ float g_cs0[3 * 256];
static __device__ float g_c[3 * 1024];
static __device__ float g_r0[3 * P_PATH * 256];
static __device__ float g_gates[3 * P_PATH * 1024];
static __device__ float g_q1[3 * P_PATH * 256];
static __device__ float g_r1[3 * P_PATH * 256];
static __device__ float g_xg[P_PATH];

__device__ __forceinline__ float sigm(float x) { return 1.f / (1.f + __expf(-x)); }

// ---------------- edge scatter: agg[dst] += h[src] ----------------
template <int D>
__global__ void scatter_add_k(const float* __restrict__ h, const int* __restrict__ src,
                              const int* __restrict__ dst, float* __restrict__ agg, int E) {
    constexpr int C = D / 4;
    int idx = blockIdx.x * blockDim.x + threadIdx.x;
    if (idx >= E * C) return;
    int e = idx / C;
    int c = idx - e * C;
    int s = src[e], t = dst[e];
    float4 v = *reinterpret_cast<const float4*>(h + (size_t)s * D + 4 * c);
    float* a = agg + (size_t)t * D + 4 * c;
    atomicAdd(a + 0, v.x);
    atomicAdd(a + 1, v.y);
    atomicAdd(a + 2, v.z);
    atomicAdd(a + 3, v.w);
}

// ---------------- GIN layer GEMM: out = relu((h+agg) @ W^T + b) ----------------
// W: [N, K] row-major. Block: 256 threads, RPB=16 rows; W cached in smem (padded).
template <int K, int N>
__global__ void gin_gemm(const float* __restrict__ h, const float* __restrict__ agg,
                         const float* __restrict__ W, const float* __restrict__ b,
                         float* __restrict__ out, int nrows) {
    constexpr int RPB = 16;
    constexpr int LDK = K + 4;  // pad (multiple of 4) to break smem bank conflicts
    extern __shared__ float sm[];
    float* sW = sm;                 // LDK*N
    float* sR = sm + LDK * N;       // RPB*K
    int tid = threadIdx.x;
    for (int i = tid; i < K * N; i += blockDim.x) {
        int j = i / K, k = i - j * K;
        sW[j * LDK + k] = W[i];
    }
    int row0 = blockIdx.x * RPB;
    for (int i = tid; i < RPB * K; i += blockDim.x) {
        int r = i / K, k = i - r * K;
        int row = row0 + r;
        sR[i] = (row < nrows) ? (h[(size_t)row * K + k] + agg[(size_t)row * K + k]) : 0.f;
    }
    __syncthreads();
    int j = tid;
    if (j < N) {
        float acc[RPB];
#pragma unroll
        for (int r = 0; r < RPB; r++) acc[r] = 0.f;
        for (int k = 0; k < K; k += 4) {
            float4 w4 = *reinterpret_cast<const float4*>(&sW[j * LDK + k]);
#pragma unroll
            for (int r = 0; r < RPB; r++) {
                float4 s4 = *reinterpret_cast<const float4*>(&sR[r * K + k]);
                acc[r] += s4.x * w4.x + s4.y * w4.y + s4.z * w4.z + s4.w * w4.w;
            }
        }
        float bj = b[j];
#pragma unroll
        for (int r = 0; r < RPB; r++) {
            int row = row0 + r;
            if (row < nrows) out[(size_t)row * N + j] = fmaxf(acc[r] + bj, 0.f);
        }
    }
}

// ---------------- gather x[p,s,:] = h4[path_nodes[p,s],:] ----------------
__global__ void gather_kernel(const float* __restrict__ h4, const int* __restrict__ pn,
                              float* __restrict__ x) {
    int idx = blockIdx.x * blockDim.x + threadIdx.x;  // P*S*64 float4 chunks
    if (idx >= P_PATH * S_SUB * 64) return;
    int c = idx & 63;
    int ps = idx >> 6;
    int node = pn[ps];
    reinterpret_cast<float4*>(x)[(size_t)ps * 64 + c] =
        reinterpret_cast<const float4*>(h4)[(size_t)node * 64 + c];
}

// ---------------- Set2Set iter-0 constants: q_star=hs=cs=0 -> gates = bih+bhh ----------------
__global__ void s2s_init(const float* __restrict__ bih, const float* __restrict__ bhh,
                         float* __restrict__ cs0, float* __restrict__ q0) {
    int idx = blockIdx.x * blockDim.x + threadIdx.x;
    if (idx >= 3 * 256) return;
    int k = idx >> 8, d = idx & 255;
    const float* bi = bih + k * 1024;
    const float* bh = bhh + k * 1024;
    float gi = bi[d] + bh[d];
    float gg = bi[512 + d] + bh[512 + d];
    float go = bi[768 + d] + bh[768 + d];
    float cs = sigm(gi) * tanhf(gg);  // sig(f)*cs_prev term is zero (cs init 0)
    cs0[idx] = cs;
    q0[idx] = sigm(go) * tanhf(cs);
}

// c[k,j] = bih+bhh + sum_d q0[k,d]*(Wih[k,j,d] + Whh[k,j,d])   (hs after iter0 == q0)
__global__ void s2s_cvec(const float* __restrict__ Wih, const float* __restrict__ Whh,
                         const float* __restrict__ bih, const float* __restrict__ bhh,
                         const float* __restrict__ q0, float* __restrict__ c) {
    int k = blockIdx.y;
    int j = blockIdx.x * 256 + threadIdx.x;
    __shared__ __align__(16) float sq[256];
    sq[threadIdx.x] = q0[k * 256 + threadIdx.x];
    __syncthreads();
    const float* wi = Wih + ((size_t)k * 1024 + j) * 512;
    const float* wh = Whh + ((size_t)k * 1024 + j) * 256;
    float acc = bih[k * 1024 + j] + bhh[k * 1024 + j];
    for (int d = 0; d < 256; d += 4) {
        float4 a = *reinterpret_cast<const float4*>(wi + d);
        float4 bq = *reinterpret_cast<const float4*>(wh + d);
        float4 s = *reinterpret_cast<const float4*>(&sq[d]);
        acc += (a.x + bq.x) * s.x + (a.y + bq.y) * s.y + (a.z + bq.z) * s.z + (a.w + bq.w) * s.w;
    }
    c[k * 1024 + j] = acc;
}

// ---------------- attention: alpha = softmax_s(x . q); r = sum_s alpha * x ----------------
__global__ void attn_kernel(const float* __restrict__ x, const float* __restrict__ query,
                            int perP, float* __restrict__ rout) {
    int p = blockIdx.x, k = blockIdx.y;
    const float* q = query + (perP ? ((size_t)(k * P_PATH + p) * 256) : ((size_t)k * 256));
    __shared__ float sq[256];
    __shared__ float dots[64];
    int tid = threadIdx.x;
    sq[tid] = q[tid];
    __syncthreads();
    int w = tid >> 5, lane = tid & 31;
    const float* xp = x + (size_t)p * S_SUB * 256;
    for (int s = w; s < 64; s += 8) {
        const float* xr = xp + s * 256;
        int d0 = lane * 8;
        float part = 0.f;
#pragma unroll
        for (int m = 0; m < 8; m++) part += xr[d0 + m] * sq[d0 + m];
        for (int off = 16; off; off >>= 1) part += __shfl_down_sync(0xffffffffu, part, off);
        if (lane == 0) dots[s] = part;
    }
    __syncthreads();
    if (w == 0) {
        float a = dots[lane], b = dots[lane + 32];
        float mx = fmaxf(a, b);
        for (int off = 16; off; off >>= 1) mx = fmaxf(mx, __shfl_xor_sync(0xffffffffu, mx, off));
        float e0 = __expf(a - mx), e1 = __expf(b - mx);
        float sum = e0 + e1;
        for (int off = 16; off; off >>= 1) sum += __shfl_xor_sync(0xffffffffu, sum, off);
        float inv = 1.f / sum;
        dots[lane] = e0 * inv;
        dots[lane + 32] = e1 * inv;
    }
    __syncthreads();
    float acc = 0.f;
#pragma unroll 4
    for (int s = 0; s < 64; s++) acc += dots[s] * xp[s * 256 + tid];
    rout[((size_t)k * P_PATH + p) * 256 + tid] = acc;
}

// ---------------- gates1 = c[k,:] + r0 @ Wih[:, D:2D]^T ----------------
__global__ void gates_gemm(const float* __restrict__ r0, const float* __restrict__ Wih,
                           const float* __restrict__ c, float* __restrict__ gates) {
    int ct = blockIdx.x, rt = blockIdx.y, k = blockIdx.z;
    __shared__ __align__(16) float sR[16 * 256];
    int tid = threadIdx.x;
    const float* rbase = r0 + ((size_t)k * P_PATH + rt * 16) * 256;
    for (int i = tid; i < 16 * 256; i += 256) sR[i] = rbase[i];
    __syncthreads();
    int j = ct * 256 + tid;
    const float* wrow = Wih + ((size_t)k * 1024 + j) * 512 + 256;
    float acc[16];
#pragma unroll
    for (int r = 0; r < 16; r++) acc[r] = 0.f;
    for (int d = 0; d < 256; d += 4) {
        float4 w4 = *reinterpret_cast<const float4*>(wrow + d);
#pragma unroll
        for (int r = 0; r < 16; r++) {
            float4 s4 = *reinterpret_cast<const float4*>(&sR[r * 256 + d]);
            acc[r] += s4.x * w4.x + s4.y * w4.y + s4.z * w4.z + s4.w * w4.w;
        }
    }
    float cj = c[k * 1024 + j];
#pragma unroll
    for (int r = 0; r < 16; r++)
        gates[((size_t)k * P_PATH + rt * 16 + r) * 1024 + j] = acc[r] + cj;
}

// ---------------- iter-1 LSTM elementwise -> q1 ----------------
__global__ void lstm_kernel(const float* __restrict__ gates, const float* __restrict__ cs0,
                            float* __restrict__ q1) {
    int idx = blockIdx.x * blockDim.x + threadIdx.x;
    if (idx >= 3 * P_PATH * 256) return;
    int d = idx & 255;
    int pk = idx >> 8;  // k*512 + p
    int k = pk >> 9;
    const float* g = gates + (size_t)pk * 1024;
    float gi = g[d], gf = g[256 + d], gg = g[512 + d], go = g[768 + d];
    float cs = sigm(gf) * cs0[k * 256 + d] + sigm(gi) * tanhf(gg);
    q1[idx] = sigm(go) * tanhf(cs);
}

// ---------------- xg[p] = bg + sum_k (q1_k . Wg_q + r1_k . Wg_r) ----------------
__global__ void xg_kernel(const float* __restrict__ q1, const float* __restrict__ r1,
                          const float* __restrict__ Wg, const float* __restrict__ bg,
                          float* __restrict__ xg) {
    int p = blockIdx.x, tid = threadIdx.x;
    float acc = 0.f;
#pragma unroll
    for (int k = 0; k < 3; k++) {
        acc += q1[((size_t)k * P_PATH + p) * 256 + tid] * Wg[k * 512 + tid];
        acc += r1[((size_t)k * P_PATH + p) * 256 + tid] * Wg[k * 512 + 256 + tid];
    }
    __shared__ float sred[8];
    for (int off = 16; off; off >>= 1) acc += __shfl_xor_sync(0xffffffffu, acc, off);
    if ((tid & 31) == 0) sred[tid >> 5] = acc;
    __syncthreads();
    if (tid == 0) {
        float t = 0.f;
#pragma unroll
        for (int i = 0; i < 8; i++) t += sred[i];
        xg[p] = t + bg[0];
    }
}

// ---------------- final MLP: [1,512] -> tanh 256 -> relu 64 -> sigmoid 1 ----------------
__global__ void final_kernel(const float* __restrict__ xg, const float* __restrict__ Wl1,
                             const float* __restrict__ bl1, const float* __restrict__ Wl2,
                             const float* __restrict__ bl2, const float* __restrict__ Wl3,
                             const float* __restrict__ bl3, float* __restrict__ out) {
    __shared__ __align__(16) float sxg[512];
    __shared__ __align__(16) float sz1[256];
    __shared__ float sz2[64];
    int tid = threadIdx.x;
    sxg[tid] = xg[tid];
    sxg[tid + 256] = xg[tid + 256];
    __syncthreads();
    {
        float a = bl1[tid];
        const float* w = Wl1 + (size_t)tid * 512;
        for (int p = 0; p < 512; p += 4) {
            float4 w4 = *reinterpret_cast<const float4*>(w + p);
            float4 x4 = *reinterpret_cast<const float4*>(&sxg[p]);
            a += w4.x * x4.x + w4.y * x4.y + w4.z * x4.z + w4.w * x4.w;
        }
        sz1[tid] = tanhf(a);
    }
    __syncthreads();
    if (tid < 64) {
        float b = bl2[tid];
        const float* w2 = Wl2 + (size_t)tid * 256;
        for (int h = 0; h < 256; h += 4) {
            float4 w4 = *reinterpret_cast<const float4*>(w2 + h);
            float4 z4 = *reinterpret_cast<const float4*>(&sz1[h]);
            b += w4.x * z4.x + w4.y * z4.y + w4.z * z4.z + w4.w * z4.w;
        }
        sz2[tid] = fmaxf(b, 0.f);
    }
    __syncthreads();
    if (tid == 0) {
        float cacc = bl3[0];
        for (int j = 0; j < 64; j++) cacc += sz2[j] * Wl3[j];
        out[0] = 1.f / (1.f + __expf(-cacc));
    }
}

// ---------------- host launcher ----------------
extern "C" void kernel_launch(void* const* d_in, const int* in_sizes, int n_in,
                              void* d_out, int out_size) {
    const float* h = (const float*)d_in[0];
    const int* src = (const int*)d_in[1];
    const int* dst = (const int*)d_in[2];
    const int* pn = (const int*)d_in[3];
    const float* W1 = (const float*)d_in[4];
    const float* b1 = (const float*)d_in[5];
    const float* W2 = (const float*)d_in[6];
    const float* b2 = (const float*)d_in[7];
    const float* W3 = (const float*)d_in[8];
    const float* b3 = (const float*)d_in[9];
    const float* W4 = (const float*)d_in[10];
    const float* b4 = (const float*)d_in[11];
    const float* Wih = (const float*)d_in[12];
    const float* Whh = (const float*)d_in[13];
    const float* bih = (const float*)d_in[14];
    const float* bhh = (const float*)d_in[15];
    const float* Wg = (const float*)d_in[16];
    const float* bg = (const float*)d_in[17];
    const float* Wl1 = (const float*)d_in[18];
    const float* bl1 = (const float*)d_in[19];
    const float* Wl2 = (const float*)d_in[20];
    const float* bl2 = (const float*)d_in[21];
    const float* Wl3 = (const float*)d_in[22];
    const float* bl3 = (const float*)d_in[23];
    int E = in_sizes[1];
    float* out = (float*)d_out;

    float *agg, *h1, *h2, *h3, *h4, *x, *q0, *cs0, *cvec, *r0, *gates, *q1, *r1, *xg;
    cudaGetSymbolAddress((void**)&agg, g_agg);
    cudaGetSymbolAddress((void**)&h1, g_h1);
    cudaGetSymbolAddress((void**)&h2, g_h2);
    cudaGetSymbolAddress((void**)&h3, g_h3);
    cudaGetSymbolAddress((void**)&h4, g_h4);
    cudaGetSymbolAddress((void**)&x, g_x);
    cudaGetSymbolAddress((void**)&q0, g_q0);
    cudaGetSymbolAddress((void**)&cs0, g_cs0);
    cudaGetSymbolAddress((void**)&cvec, g_c);
    cudaGetSymbolAddress((void**)&r0, g_r0);
    cudaGetSymbolAddress((void**)&gates, g_gates);
    cudaGetSymbolAddress((void**)&q1, g_q1);
    cudaGetSymbolAddress((void**)&r1, g_r1);
    cudaGetSymbolAddress((void**)&xg, g_xg);

    const int smem1 = (12 * 24 + 16 * 8) * 4;
    const int smem2 = (28 * 64 + 16 * 24) * 4;
    const int smem3 = (68 * 128 + 16 * 64) * 4;
    const int smem4 = (132 * 256 + 16 * 128) * 4;  // ~140 KB
    cudaFuncSetAttribute(gin_gemm<64, 128>, cudaFuncAttributeMaxDynamicSharedMemorySize, smem3);
    cudaFuncSetAttribute(gin_gemm<128, 256>, cudaFuncAttributeMaxDynamicSharedMemorySize, smem4);

    const int nblocks_gin = (NN + 15) / 16;

    // layer 1: 8 -> 24
    cudaMemsetAsync(agg, 0, (size_t)NN * 8 * 4);
    scatter_add_k<8><<<(E * 2 + 255) / 256, 256>>>(h, src, dst, agg, E);
    gin_gemm<8, 24><<<nblocks_gin, 256, smem1>>>(h, agg, W1, b1, h1, NN);
    // layer 2: 24 -> 64
    cudaMemsetAsync(agg, 0, (size_t)NN * 24 * 4);
    scatter_add_k<24><<<(E * 6 + 255) / 256, 256>>>(h1, src, dst, agg, E);
    gin_gemm<24, 64><<<nblocks_gin, 256, smem2>>>(h1, agg, W2, b2, h2, NN);
    // layer 3: 64 -> 128
    cudaMemsetAsync(agg, 0, (size_t)NN * 64 * 4);
    scatter_add_k<64><<<(E * 16 + 255) / 256, 256>>>(h2, src, dst, agg, E);
    gin_gemm<64, 128><<<nblocks_gin, 256, smem3>>>(h2, agg, W3, b3, h3, NN);
    // layer 4: 128 -> 256
    cudaMemsetAsync(agg, 0, (size_t)NN * 128 * 4);
    scatter_add_k<128><<<(E * 32 + 255) / 256, 256>>>(h3, src, dst, agg, E);
    gin_gemm<128, 256><<<nblocks_gin, 256, smem4>>>(h3, agg, W4, b4, h4, NN);

    // pathway gather
    gather_kernel<<<(P_PATH * S_SUB * 64 + 255) / 256, 256>>>(h4, pn, x);

    // Set2Set (all 3 modules batched in grid.y/.z)
    s2s_init<<<3, 256>>>(bih, bhh, cs0, q0);
    attn_kernel<<<dim3(P_PATH, 3), 256>>>(x, q0, 0, r0);
    s2s_cvec<<<dim3(4, 3), 256>>>(Wih, Whh, bih, bhh, q0, cvec);
    gates_gemm<<<dim3(4, P_PATH / 16, 3), 256>>>(r0, Wih, cvec, gates);
    lstm_kernel<<<(3 * P_PATH * 256 + 255) / 256, 256>>>(gates, cs0, q1);
    attn_kernel<<<dim3(P_PATH, 3), 256>>>(x, q1, 1, r1);

    xg_kernel<<<P_PATH, 256>>>(q1, r1, Wg, bg, xg);
    final_kernel<<<1, 256>>>(xg, Wl1, bl1, Wl2, bl2, Wl3, bl3, out);
}

// round 2
// speedup vs baseline: 1.4998x; 1.4998x over previous
#include <cuda_runtime.h>
#include <cuda_bf16.h>
#include <cstdint>

#define NN 20000
#define NE 640000
#define P_PATH 512
#define S_SUB 64
#define DHID 256

// ---------------- scratch (static device globals; no allocation) ----------------
static __device__ float g_agg[NN * 128];      // aggregation output (reused per layer)
static __device__ float g_h1[NN * 24];
static __device__ float g_h2[NN * 64];
static __device__ float g_h3[NN * 128];
static __device__ float g_h4[NN * 256];
static __device__ int g_deg[NN];
static __device__ int g_off[NN + 1];
static __device__ int g_cur[NN];
static __device__ int g_srcs[NE];
static __device__ float g_x[P_PATH * S_SUB * DHID];
static __device__ float g_q0[3 * 256];
static __device__ float g_cs0[3 * 256];
static __device__ float g_c[3 * 1024];
static __device__ float g_r0[3 * P_PATH * 256];
static __device__ float g_gates[3 * P_PATH * 1024];
static __device__ float g_q1[3 * P_PATH * 256];
static __device__ float g_r1[3 * P_PATH * 256];
static __device__ float g_xg[P_PATH];

__device__ __forceinline__ float sigm(float x) { return 1.f / (1.f + __expf(-x)); }

// ---------------- CSR build ----------------
__global__ void hist_kernel(const int* __restrict__ dst, int* __restrict__ deg, int E) {
    int e = blockIdx.x * blockDim.x + threadIdx.x;
    if (e < E) atomicAdd(&deg[dst[e]], 1);
}

__global__ void scan_kernel(const int* __restrict__ deg, int* __restrict__ off,
                            int* __restrict__ cur) {
    __shared__ int part[1024];
    int t = threadIdx.x;
    const int CH = (NN + 1023) / 1024;  // 20
    int start = t * CH;
    int end = min(start + CH, NN);
    int s = 0;
    for (int i = start; i < end; i++) s += deg[i];
    part[t] = s;
    __syncthreads();
    for (int o = 1; o < 1024; o <<= 1) {
        int v = (t >= o) ? part[t - o] : 0;
        __syncthreads();
        part[t] += v;
        __syncthreads();
    }
    int base = (t > 0) ? part[t - 1] : 0;
    for (int i = start; i < end; i++) {
        off[i] = base;
        cur[i] = base;
        base += deg[i];
    }
    if (t == 1023) off[NN] = part[1023];
}

__global__ void bucket_kernel(const int* __restrict__ src, const int* __restrict__ dst,
                              int* __restrict__ cur, int* __restrict__ srcs, int E) {
    int e = blockIdx.x * blockDim.x + threadIdx.x;
    if (e < E) {
        int p = atomicAdd(&cur[dst[e]], 1);
        srcs[p] = src[e];
    }
}

// ---------------- gather aggregation: out[i] = h[i] + sum_{j in N(i)} h[j] ----------------
template <int D>
__global__ void aggregate_k(const float* __restrict__ h, const int* __restrict__ off,
                            const int* __restrict__ srcs, float* __restrict__ outp) {
    constexpr int C = D / 4;
    int idx = blockIdx.x * blockDim.x + threadIdx.x;
    if (idx >= NN * C) return;
    int node = idx / C;
    int c = idx - node * C;
    const float4* hp = reinterpret_cast<const float4*>(h);
    float4 acc = hp[(size_t)node * C + c];
    int s0 = off[node], s1 = off[node + 1];
#pragma unroll 4
    for (int j = s0; j < s1; j++) {
        int s = __ldg(&srcs[j]);
        float4 v = hp[(size_t)s * C + c];
        acc.x += v.x;
        acc.y += v.y;
        acc.z += v.z;
        acc.w += v.w;
    }
    reinterpret_cast<float4*>(outp)[idx] = acc;
}

// ---------------- GIN GEMM: out = relu(xin @ W^T + b) ----------------
// W: [N,K] row-major. 256 threads; block handles RPB=32 rows.
// thread -> col j = tid % NP (NP = padded N dividing 256), row-group rg = tid / NP.
template <int K, int N, int NP>
__global__ void gemm_relu(const float* __restrict__ xin, const float* __restrict__ W,
                          const float* __restrict__ b, float* __restrict__ out, int nrows) {
    constexpr int RPB = 32;
    constexpr int LDK = K + 4;
    constexpr int G = 256 / NP;
    constexpr int RPT = RPB / G;
    extern __shared__ float sm[];
    float* sW = sm;            // N * LDK
    float* sR = sm + N * LDK;  // RPB * K
    int tid = threadIdx.x;
    for (int i = tid; i < K * N; i += 256) {
        int j = i / K, k = i - j * K;
        sW[j * LDK + k] = W[i];
    }
    int row0 = blockIdx.x * RPB;
    for (int i = tid; i < RPB * K; i += 256) {
        int r = i / K, k = i - r * K;
        int row = row0 + r;
        sR[i] = (row < nrows) ? xin[(size_t)row * K + k] : 0.f;
    }
    __syncthreads();
    int j = tid % NP;
    int rg = tid / NP;
    if (j < N) {
        float acc[RPT];
#pragma unroll
        for (int t = 0; t < RPT; t++) acc[t] = 0.f;
        for (int k = 0; k < K; k += 4) {
            float4 w4 = *reinterpret_cast<const float4*>(&sW[j * LDK + k]);
#pragma unroll
            for (int t = 0; t < RPT; t++) {
                float4 s4 = *reinterpret_cast<const float4*>(&sR[(rg + t * G) * K + k]);
                acc[t] += s4.x * w4.x + s4.y * w4.y + s4.z * w4.z + s4.w * w4.w;
            }
        }
        float bj = b[j];
#pragma unroll
        for (int t = 0; t < RPT; t++) {
            int row = row0 + rg + t * G;
            if (row < nrows) out[(size_t)row * N + j] = fmaxf(acc[t] + bj, 0.f);
        }
    }
}

// ---------------- gather x[p,s,:] = h4[path_nodes[p,s],:] ----------------
__global__ void gather_kernel(const float* __restrict__ h4, const int* __restrict__ pn,
                              float* __restrict__ x) {
    int idx = blockIdx.x * blockDim.x + threadIdx.x;  // P*S*64 float4 chunks
    if (idx >= P_PATH * S_SUB * 64) return;
    int c = idx & 63;
    int ps = idx >> 6;
    int node = pn[ps];
    reinterpret_cast<float4*>(x)[(size_t)ps * 64 + c] =
        reinterpret_cast<const float4*>(h4)[(size_t)node * 64 + c];
}

// ---------------- Set2Set iter-0 constants: q_star=hs=cs=0 -> gates = bih+bhh ----------------
__global__ void s2s_init(const float* __restrict__ bih, const float* __restrict__ bhh,
                         float* __restrict__ cs0, float* __restrict__ q0) {
    int idx = blockIdx.x * blockDim.x + threadIdx.x;
    if (idx >= 3 * 256) return;
    int k = idx >> 8, d = idx & 255;
    const float* bi = bih + k * 1024;
    const float* bh = bhh + k * 1024;
    float gi = bi[d] + bh[d];
    float gg = bi[512 + d] + bh[512 + d];
    float go = bi[768 + d] + bh[768 + d];
    float cs = sigm(gi) * tanhf(gg);
    cs0[idx] = cs;
    q0[idx] = sigm(go) * tanhf(cs);
}

// c[k,j] = bih+bhh + sum_d q0[k,d]*(Wih[k,j,d] + Whh[k,j,d])
__global__ void s2s_cvec(const float* __restrict__ Wih, const float* __restrict__ Whh,
                         const float* __restrict__ bih, const float* __restrict__ bhh,
                         const float* __restrict__ q0, float* __restrict__ c) {
    int k = blockIdx.y;
    int j = blockIdx.x * 256 + threadIdx.x;
    __shared__ __align__(16) float sq[256];
    sq[threadIdx.x] = q0[k * 256 + threadIdx.x];
    __syncthreads();
    const float* wi = Wih + ((size_t)k * 1024 + j) * 512;
    const float* wh = Whh + ((size_t)k * 1024 + j) * 256;
    float acc = bih[k * 1024 + j] + bhh[k * 1024 + j];
    for (int d = 0; d < 256; d += 4) {
        float4 a = *reinterpret_cast<const float4*>(wi + d);
        float4 bq = *reinterpret_cast<const float4*>(wh + d);
        float4 s = *reinterpret_cast<const float4*>(&sq[d]);
        acc += (a.x + bq.x) * s.x + (a.y + bq.y) * s.y + (a.z + bq.z) * s.z + (a.w + bq.w) * s.w;
    }
    c[k * 1024 + j] = acc;
}

// ---------------- attention: alpha = softmax_s(x . q); r = sum_s alpha * x ----------------
__global__ void attn_kernel(const float* __restrict__ x, const float* __restrict__ query,
                            int perP, float* __restrict__ rout) {
    int p = blockIdx.x, k = blockIdx.y;
    const float* q = query + (perP ? ((size_t)(k * P_PATH + p) * 256) : ((size_t)k * 256));
    __shared__ float sq[256];
    __shared__ float dots[64];
    int tid = threadIdx.x;
    sq[tid] = q[tid];
    __syncthreads();
    int w = tid >> 5, lane = tid & 31;
    const float* xp = x + (size_t)p * S_SUB * 256;
    for (int s = w; s < 64; s += 8) {
        const float* xr = xp + s * 256;
        int d0 = lane * 8;
        float part = 0.f;
#pragma unroll
        for (int m = 0; m < 8; m++) part += xr[d0 + m] * sq[d0 + m];
        for (int off = 16; off; off >>= 1) part += __shfl_down_sync(0xffffffffu, part, off);
        if (lane == 0) dots[s] = part;
    }
    __syncthreads();
    if (w == 0) {
        float a = dots[lane], b = dots[lane + 32];
        float mx = fmaxf(a, b);
        for (int off = 16; off; off >>= 1) mx = fmaxf(mx, __shfl_xor_sync(0xffffffffu, mx, off));
        float e0 = __expf(a - mx), e1 = __expf(b - mx);
        float sum = e0 + e1;
        for (int off = 16; off; off >>= 1) sum += __shfl_xor_sync(0xffffffffu, sum, off);
        float inv = 1.f / sum;
        dots[lane] = e0 * inv;
        dots[lane + 32] = e1 * inv;
    }
    __syncthreads();
    float acc = 0.f;
#pragma unroll 4
    for (int s = 0; s < 64; s++) acc += dots[s] * xp[s * 256 + tid];
    rout[((size_t)k * P_PATH + p) * 256 + tid] = acc;
}

// ---------------- gates1 = c[k,:] + r0 @ Wih[:, D:2D]^T ----------------
__global__ void gates_gemm(const float* __restrict__ r0, const float* __restrict__ Wih,
                           const float* __restrict__ c, float* __restrict__ gates) {
    int ct = blockIdx.x, rt = blockIdx.y, k = blockIdx.z;
    __shared__ __align__(16) float sR[16 * 256];
    int tid = threadIdx.x;
    const float* rbase = r0 + ((size_t)k * P_PATH + rt * 16) * 256;
    for (int i = tid; i < 16 * 256; i += 256) sR[i] = rbase[i];
    __syncthreads();
    int j = ct * 256 + tid;
    const float* wrow = Wih + ((size_t)k * 1024 + j) * 512 + 256;
    float acc[16];
#pragma unroll
    for (int r = 0; r < 16; r++) acc[r] = 0.f;
    for (int d = 0; d < 256; d += 4) {
        float4 w4 = *reinterpret_cast<const float4*>(wrow + d);
#pragma unroll
        for (int r = 0; r < 16; r++) {
            float4 s4 = *reinterpret_cast<const float4*>(&sR[r * 256 + d]);
            acc[r] += s4.x * w4.x + s4.y * w4.y + s4.z * w4.z + s4.w * w4.w;
        }
    }
    float cj = c[k * 1024 + j];
#pragma unroll
    for (int r = 0; r < 16; r++)
        gates[((size_t)k * P_PATH + rt * 16 + r) * 1024 + j] = acc[r] + cj;
}

// ---------------- iter-1 LSTM elementwise -> q1 ----------------
__global__ void lstm_kernel(const float* __restrict__ gates, const float* __restrict__ cs0,
                            float* __restrict__ q1) {
    int idx = blockIdx.x * blockDim.x + threadIdx.x;
    if (idx >= 3 * P_PATH * 256) return;
    int d = idx & 255;
    int pk = idx >> 8;
    int k = pk >> 9;
    const float* g = gates + (size_t)pk * 1024;
    float gi = g[d], gf = g[256 + d], gg = g[512 + d], go = g[768 + d];
    float cs = sigm(gf) * cs0[k * 256 + d] + sigm(gi) * tanhf(gg);
    q1[idx] = sigm(go) * tanhf(cs);
}

// ---------------- xg[p] = bg + sum_k (q1_k . Wg_q + r1_k . Wg_r) ----------------
__global__ void xg_kernel(const float* __restrict__ q1, const float* __restrict__ r1,
                          const float* __restrict__ Wg, const float* __restrict__ bg,
                          float* __restrict__ xg) {
    int p = blockIdx.x, tid = threadIdx.x;
    float acc = 0.f;
#pragma unroll
    for (int k = 0; k < 3; k++) {
        acc += q1[((size_t)k * P_PATH + p) * 256 + tid] * Wg[k * 512 + tid];
        acc += r1[((size_t)k * P_PATH + p) * 256 + tid] * Wg[k * 512 + 256 + tid];
    }
    __shared__ float sred[8];
    for (int off = 16; off; off >>= 1) acc += __shfl_xor_sync(0xffffffffu, acc, off);
    if ((tid & 31) == 0) sred[tid >> 5] = acc;
    __syncthreads();
    if (tid == 0) {
        float t = 0.f;
#pragma unroll
        for (int i = 0; i < 8; i++) t += sred[i];
        xg[p] = t + bg[0];
    }
}

// ---------------- final MLP: [1,512] -> tanh 256 -> relu 64 -> sigmoid 1 ----------------
__global__ void final_kernel(const float* __restrict__ xg, const float* __restrict__ Wl1,
                             const float* __restrict__ bl1, const float* __restrict__ Wl2,
                             const float* __restrict__ bl2, const float* __restrict__ Wl3,
                             const float* __restrict__ bl3, float* __restrict__ out) {
    __shared__ __align__(16) float sxg[512];
    __shared__ __align__(16) float sz1[256];
    __shared__ float sz2[64];
    int tid = threadIdx.x;
    sxg[tid] = xg[tid];
    sxg[tid + 256] = xg[tid + 256];
    __syncthreads();
    {
        float a = bl1[tid];
        const float* w = Wl1 + (size_t)tid * 512;
        for (int p = 0; p < 512; p += 4) {
            float4 w4 = *reinterpret_cast<const float4*>(w + p);
            float4 x4 = *reinterpret_cast<const float4*>(&sxg[p]);
            a += w4.x * x4.x + w4.y * x4.y + w4.z * x4.z + w4.w * x4.w;
        }
        sz1[tid] = tanhf(a);
    }
    __syncthreads();
    if (tid < 64) {
        float bacc = bl2[tid];
        const float* w2 = Wl2 + (size_t)tid * 256;
        for (int hh = 0; hh < 256; hh += 4) {
            float4 w4 = *reinterpret_cast<const float4*>(w2 + hh);
            float4 z4 = *reinterpret_cast<const float4*>(&sz1[hh]);
            bacc += w4.x * z4.x + w4.y * z4.y + w4.z * z4.z + w4.w * z4.w;
        }
        sz2[tid] = fmaxf(bacc, 0.f);
    }
    __syncthreads();
    if (tid == 0) {
        float cacc = bl3[0];
        for (int j = 0; j < 64; j++) cacc += sz2[j] * Wl3[j];
        out[0] = 1.f / (1.f + __expf(-cacc));
    }
}

// ---------------- host launcher ----------------
extern "C" void kernel_launch(void* const* d_in, const int* in_sizes, int n_in,
                              void* d_out, int out_size) {
    const float* h = (const float*)d_in[0];
    const int* src = (const int*)d_in[1];
    const int* dst = (const int*)d_in[2];
    const int* pn = (const int*)d_in[3];
    const float* W1 = (const float*)d_in[4];
    const float* b1 = (const float*)d_in[5];
    const float* W2 = (const float*)d_in[6];
    const float* b2 = (const float*)d_in[7];
    const float* W3 = (const float*)d_in[8];
    const float* b3 = (const float*)d_in[9];
    const float* W4 = (const float*)d_in[10];
    const float* b4 = (const float*)d_in[11];
    const float* Wih = (const float*)d_in[12];
    const float* Whh = (const float*)d_in[13];
    const float* bih = (const float*)d_in[14];
    const float* bhh = (const float*)d_in[15];
    const float* Wg = (const float*)d_in[16];
    const float* bg = (const float*)d_in[17];
    const float* Wl1 = (const float*)d_in[18];
    const float* bl1 = (const float*)d_in[19];
    const float* Wl2 = (const float*)d_in[20];
    const float* bl2 = (const float*)d_in[21];
    const float* Wl3 = (const float*)d_in[22];
    const float* bl3 = (const float*)d_in[23];
    int E = in_sizes[1];
    float* out = (float*)d_out;

    float *agg, *h1, *h2, *h3, *h4, *x, *q0, *cs0, *cvec, *r0, *gates, *q1, *r1, *xg;
    int *deg, *off, *cur, *srcs;
    cudaGetSymbolAddress((void**)&agg, g_agg);
    cudaGetSymbolAddress((void**)&h1, g_h1);
    cudaGetSymbolAddress((void**)&h2, g_h2);
    cudaGetSymbolAddress((void**)&h3, g_h3);
    cudaGetSymbolAddress((void**)&h4, g_h4);
    cudaGetSymbolAddress((void**)&x, g_x);
    cudaGetSymbolAddress((void**)&q0, g_q0);
    cudaGetSymbolAddress((void**)&cs0, g_cs0);
    cudaGetSymbolAddress((void**)&cvec, g_c);
    cudaGetSymbolAddress((void**)&r0, g_r0);
    cudaGetSymbolAddress((void**)&gates, g_gates);
    cudaGetSymbolAddress((void**)&q1, g_q1);
    cudaGetSymbolAddress((void**)&r1, g_r1);
    cudaGetSymbolAddress((void**)&xg, g_xg);
    cudaGetSymbolAddress((void**)&deg, g_deg);
    cudaGetSymbolAddress((void**)&off, g_off);
    cudaGetSymbolAddress((void**)&cur, g_cur);
    cudaGetSymbolAddress((void**)&srcs, g_srcs);

    // smem sizes for gemm_relu<K,N,NP>: (N*(K+4) + 32*K) * 4 bytes
    const int smem1 = (24 * 12 + 32 * 8) * 4;
    const int smem2 = (64 * 28 + 32 * 24) * 4;
    const int smem3 = (128 * 68 + 32 * 64) * 4;
    const int smem4 = (256 * 132 + 32 * 128) * 4;  // ~151 KB
    cudaFuncSetAttribute(gemm_relu<64, 128, 128>, cudaFuncAttributeMaxDynamicSharedMemorySize,
                         smem3);
    cudaFuncSetAttribute(gemm_relu<128, 256, 256>, cudaFuncAttributeMaxDynamicSharedMemorySize,
                         smem4);

    const int nblk_gemm = (NN + 31) / 32;  // 625

    // ---- CSR build (once; reused by all 4 layers) ----
    cudaMemsetAsync(deg, 0, NN * sizeof(int));
    hist_kernel<<<(E + 255) / 256, 256>>>(dst, deg, E);
    scan_kernel<<<1, 1024>>>(deg, off, cur);
    bucket_kernel<<<(E + 255) / 256, 256>>>(src, dst, cur, srcs, E);

    // ---- 4 GIN layers: gather-sum then GEMM ----
    aggregate_k<8><<<(NN * 2 + 255) / 256, 256>>>(h, off, srcs, agg);
    gemm_relu<8, 24, 32><<<nblk_gemm, 256, smem1>>>(agg, W1, b1, h1, NN);

    aggregate_k<24><<<(NN * 6 + 255) / 256, 256>>>(h1, off, srcs, agg);
    gemm_relu<24, 64, 64><<<nblk_gemm, 256, smem2>>>(agg, W2, b2, h2, NN);

    aggregate_k<64><<<(NN * 16 + 255) / 256, 256>>>(h2, off, srcs, agg);
    gemm_relu<64, 128, 128><<<nblk_gemm, 256, smem3>>>(agg, W3, b3, h3, NN);

    aggregate_k<128><<<(NN * 32 + 255) / 256, 256>>>(h3, off, srcs, agg);
    gemm_relu<128, 256, 256><<<nblk_gemm, 256, smem4>>>(agg, W4, b4, h4, NN);

    // ---- pathway gather ----
    gather_kernel<<<(P_PATH * S_SUB * 64 + 255) / 256, 256>>>(h4, pn, x);

    // ---- Set2Set (3 modules batched via grid dims) ----
    s2s_init<<<3, 256>>>(bih, bhh, cs0, q0);
    attn_kernel<<<dim3(P_PATH, 3), 256>>>(x, q0, 0, r0);
    s2s_cvec<<<dim3(4, 3), 256>>>(Wih, Whh, bih, bhh, q0, cvec);
    gates_gemm<<<dim3(4, P_PATH / 16, 3), 256>>>(r0, Wih, cvec, gates);
    lstm_kernel<<<(3 * P_PATH * 256 + 255) / 256, 256>>>(gates, cs0, q1);
    attn_kernel<<<dim3(P_PATH, 3), 256>>>(x, q1, 1, r1);

    xg_kernel<<<P_PATH, 256>>>(q1, r1, Wg, bg, xg);
    final_kernel<<<1, 256>>>(xg, Wl1, bl1, Wl2, bl2, Wl3, bl3, out);
}

// round 3
// speedup vs baseline: 1.7260x; 1.1508x over previous
#include <cuda_runtime.h>
#include <cuda_bf16.h>
#include <cstdint>

#define NN 20000
#define NE 640000
#define P_PATH 512
#define S_SUB 64
#define DHID 256

// ---------------- scratch (static device globals; no allocation) ----------------
static __device__ float g_agg[NN * 128];       // aggregation output (reused per layer)
static __device__ float g_part[NN * 256];      // sliced partial sums (max NS*NN*D)
static __device__ float g_h1[NN * 24];
static __device__ float g_h2[NN * 64];
static __device__ float g_h3[NN * 128];
static __device__ float g_h4[NN * 256];
static __device__ int g_deg[NN];
static __device__ int g_off[NN + 1];
static __device__ int g_cur[NN];
static __device__ int g_srcs[NE];
static __device__ float g_q0[3 * 256];
static __device__ float g_cs0[3 * 256];
static __device__ float g_c[3 * 1024];
static __device__ float g_r0[3 * P_PATH * 256];
static __device__ float g_gates[3 * P_PATH * 1024];
static __device__ float g_q1[3 * P_PATH * 256];
static __device__ float g_r1[3 * P_PATH * 256];
static __device__ float g_xg[P_PATH];

__device__ __forceinline__ float sigm(float x) { return 1.f / (1.f + __expf(-x)); }

// ---------------- CSR build ----------------
__global__ void hist_kernel(const int* __restrict__ dst, int* __restrict__ deg, int E) {
    int e = blockIdx.x * blockDim.x + threadIdx.x;
    if (e < E) atomicAdd(&deg[dst[e]], 1);
}

__global__ void scan_kernel(const int* __restrict__ deg, int* __restrict__ off,
                            int* __restrict__ cur) {
    __shared__ int part[1024];
    int t = threadIdx.x;
    const int CH = (NN + 1023) / 1024;  // 20
    int start = t * CH;
    int end = min(start + CH, NN);
    int s = 0;
    for (int i = start; i < end; i++) s += deg[i];
    part[t] = s;
    __syncthreads();
    for (int o = 1; o < 1024; o <<= 1) {
        int v = (t >= o) ? part[t - o] : 0;
        __syncthreads();
        part[t] += v;
        __syncthreads();
    }
    int base = (t > 0) ? part[t - 1] : 0;
    for (int i = start; i < end; i++) {
        off[i] = base;
        cur[i] = base;
        base += deg[i];
    }
    if (t == 1023) off[NN] = part[1023];
}

__global__ void bucket_kernel(const int* __restrict__ src, const int* __restrict__ dst,
                              int* __restrict__ cur, int* __restrict__ srcs, int E) {
    int e = blockIdx.x * blockDim.x + threadIdx.x;
    if (e < E) {
        int p = atomicAdd(&cur[dst[e]], 1);
        srcs[p] = src[e];
    }
}

// ---------------- direct gather aggregation (large D): out[i] = h[i] + sum_{j->i} h[j] ----
template <int D>
__global__ void aggregate_k(const float* __restrict__ h, const int* __restrict__ off,
                            const int* __restrict__ srcs, float* __restrict__ outp) {
    constexpr int C = D / 4;
    int idx = blockIdx.x * blockDim.x + threadIdx.x;
    if (idx >= NN * C) return;
    int node = idx / C;
    int c = idx - node * C;
    const float4* hp = reinterpret_cast<const float4*>(h);
    float4 acc = hp[(size_t)node * C + c];
    int s0 = off[node], s1 = off[node + 1];
#pragma unroll 8
    for (int j = s0; j < s1; j++) {
        int s = __ldg(&srcs[j]);
        float4 v = hp[(size_t)s * C + c];
        acc.x += v.x;
        acc.y += v.y;
        acc.z += v.z;
        acc.w += v.w;
    }
    reinterpret_cast<float4*>(outp)[idx] = acc;
}

// ---------------- sliced aggregation (small D): NS partial sums per node, then combine ----
template <int D, int NS>
__global__ void aggregate_sliced(const float* __restrict__ h, const int* __restrict__ off,
                                 const int* __restrict__ srcs, float* __restrict__ part) {
    constexpr int C = D / 4;
    int idx = blockIdx.x * blockDim.x + threadIdx.x;
    if (idx >= NN * C * NS) return;
    int slice = idx / (NN * C);
    int rem = idx - slice * NN * C;
    int node = rem / C;
    int c = rem - node * C;
    const float4* hp = reinterpret_cast<const float4*>(h);
    int s0 = off[node], s1 = off[node + 1];
    int len = s1 - s0;
    int a = s0 + (len * slice) / NS;
    int b = s0 + (len * (slice + 1)) / NS;
    float4 acc = {0.f, 0.f, 0.f, 0.f};
#pragma unroll 4
    for (int j = a; j < b; j++) {
        int s = __ldg(&srcs[j]);
        float4 v = hp[(size_t)s * C + c];
        acc.x += v.x;
        acc.y += v.y;
        acc.z += v.z;
        acc.w += v.w;
    }
    reinterpret_cast<float4*>(part)[idx] = acc;
}

template <int D, int NS>
__global__ void combine_k(const float* __restrict__ h, const float* __restrict__ part,
                          float* __restrict__ outp) {
    constexpr int C = D / 4;
    int idx = blockIdx.x * blockDim.x + threadIdx.x;
    if (idx >= NN * C) return;
    const float4* hp = reinterpret_cast<const float4*>(h);
    const float4* pp = reinterpret_cast<const float4*>(part);
    float4 acc = hp[idx];
#pragma unroll
    for (int s = 0; s < NS; s++) {
        float4 v = pp[(size_t)s * NN * C + idx];
        acc.x += v.x;
        acc.y += v.y;
        acc.z += v.z;
        acc.w += v.w;
    }
    reinterpret_cast<float4*>(outp)[idx] = acc;
}

// ---------------- GIN GEMM: out = relu(xin @ W^T + b) ----------------
// W: [N,K] row-major. T threads; block handles RPB rows.
template <int K, int N, int NP, int T, int RPB>
__global__ void gemm_relu(const float* __restrict__ xin, const float* __restrict__ W,
                          const float* __restrict__ b, float* __restrict__ out, int nrows) {
    constexpr int LDK = K + 4;
    constexpr int G = T / NP;
    constexpr int RPT = RPB / G;
    extern __shared__ float sm[];
    float* sW = sm;            // N * LDK
    float* sR = sm + N * LDK;  // RPB * K
    int tid = threadIdx.x;
    for (int i = tid; i < K * N; i += T) {
        int j = i / K, k = i - j * K;
        sW[j * LDK + k] = W[i];
    }
    int row0 = blockIdx.x * RPB;
    for (int i = tid; i < RPB * K; i += T) {
        int r = i / K, k = i - r * K;
        int row = row0 + r;
        sR[i] = (row < nrows) ? xin[(size_t)row * K + k] : 0.f;
    }
    __syncthreads();
    int j = tid % NP;
    int rg = tid / NP;
    if (j < N) {
        float acc[RPT];
#pragma unroll
        for (int t = 0; t < RPT; t++) acc[t] = 0.f;
        for (int k = 0; k < K; k += 4) {
            float4 w4 = *reinterpret_cast<const float4*>(&sW[j * LDK + k]);
#pragma unroll
            for (int t = 0; t < RPT; t++) {
                float4 s4 = *reinterpret_cast<const float4*>(&sR[(rg + t * G) * K + k]);
                acc[t] += s4.x * w4.x + s4.y * w4.y + s4.z * w4.z + s4.w * w4.w;
            }
        }
        float bj = b[j];
#pragma unroll
        for (int t = 0; t < RPT; t++) {
            int row = row0 + rg + t * G;
            if (row < nrows) out[(size_t)row * N + j] = fmaxf(acc[t] + bj, 0.f);
        }
    }
}

// ---------------- Set2Set iter-0 constants: q_star=hs=cs=0 -> gates = bih+bhh ----------------
__global__ void s2s_init(const float* __restrict__ bih, const float* __restrict__ bhh,
                         float* __restrict__ cs0, float* __restrict__ q0) {
    int idx = blockIdx.x * blockDim.x + threadIdx.x;
    if (idx >= 3 * 256) return;
    int k = idx >> 8, d = idx & 255;
    const float* bi = bih + k * 1024;
    const float* bh = bhh + k * 1024;
    float gi = bi[d] + bh[d];
    float gg = bi[512 + d] + bh[512 + d];
    float go = bi[768 + d] + bh[768 + d];
    float cs = sigm(gi) * tanhf(gg);
    cs0[idx] = cs;
    q0[idx] = sigm(go) * tanhf(cs);
}

// c[k,j] = bih+bhh + sum_d q0[k,d]*(Wih[k,j,d] + Whh[k,j,d])
__global__ void s2s_cvec(const float* __restrict__ Wih, const float* __restrict__ Whh,
                         const float* __restrict__ bih, const float* __restrict__ bhh,
                         const float* __restrict__ q0, float* __restrict__ c) {
    int k = blockIdx.y;
    int j = blockIdx.x * 256 + threadIdx.x;
    __shared__ __align__(16) float sq[256];
    sq[threadIdx.x] = q0[k * 256 + threadIdx.x];
    __syncthreads();
    const float* wi = Wih + ((size_t)k * 1024 + j) * 512;
    const float* wh = Whh + ((size_t)k * 1024 + j) * 256;
    float acc = bih[k * 1024 + j] + bhh[k * 1024 + j];
    for (int d = 0; d < 256; d += 4) {
        float4 a = *reinterpret_cast<const float4*>(wi + d);
        float4 bq = *reinterpret_cast<const float4*>(wh + d);
        float4 s = *reinterpret_cast<const float4*>(&sq[d]);
        acc += (a.x + bq.x) * s.x + (a.y + bq.y) * s.y + (a.z + bq.z) * s.z + (a.w + bq.w) * s.w;
    }
    c[k * 1024 + j] = acc;
}

// ---------------- attention (fused gather): x tile staged in smem, two passes ----------------
// smem layout: sx[64*256] | sq[256] | dots[64] | spn[64]
__global__ void attn_kernel(const float* __restrict__ h4, const int* __restrict__ pn,
                            const float* __restrict__ query, int perP,
                            float* __restrict__ rout) {
    int p = blockIdx.x, k = blockIdx.y;
    extern __shared__ float smdyn[];
    float* sx = smdyn;
    float* sq = smdyn + 64 * 256;
    float* dots = sq + 256;
    int* spn = (int*)(dots + 64);
    int tid = threadIdx.x;

    const float* q = query + (perP ? ((size_t)(k * P_PATH + p) * 256) : ((size_t)k * 256));
    sq[tid] = q[tid];
    if (tid < 64) spn[tid] = pn[p * 64 + tid];
    __syncthreads();

    // gather x tile: 64 rows x 64 float4
    const float4* h4v = reinterpret_cast<const float4*>(h4);
    float4* sxv = reinterpret_cast<float4*>(sx);
    for (int i = tid; i < 64 * 64; i += 256) {
        int s = i >> 6, c = i & 63;
        sxv[i] = h4v[(size_t)spn[s] * 64 + c];
    }
    __syncthreads();

    // dots: warp w handles rows w, w+8, ...; conflict-free strided smem reads
    int w = tid >> 5, lane = tid & 31;
    for (int s = w; s < 64; s += 8) {
        const float* xr = sx + s * 256;
        float part = 0.f;
#pragma unroll
        for (int m = 0; m < 8; m++) part += xr[lane + 32 * m] * sq[lane + 32 * m];
        for (int off = 16; off; off >>= 1) part += __shfl_down_sync(0xffffffffu, part, off);
        if (lane == 0) dots[s] = part;
    }
    __syncthreads();
    if (w == 0) {
        float a = dots[lane], b = dots[lane + 32];
        float mx = fmaxf(a, b);
        for (int off = 16; off; off >>= 1) mx = fmaxf(mx, __shfl_xor_sync(0xffffffffu, mx, off));
        float e0 = __expf(a - mx), e1 = __expf(b - mx);
        float sum = e0 + e1;
        for (int off = 16; off; off >>= 1) sum += __shfl_xor_sync(0xffffffffu, sum, off);
        float inv = 1.f / sum;
        dots[lane] = e0 * inv;
        dots[lane + 32] = e1 * inv;
    }
    __syncthreads();
    float acc = 0.f;
#pragma unroll 8
    for (int s = 0; s < 64; s++) acc += dots[s] * sx[s * 256 + tid];
    rout[((size_t)k * P_PATH + p) * 256 + tid] = acc;
}

// ---------------- gates1 = c[k,:] + r0 @ Wih[:, D:2D]^T   (32-row tiles) ----------------
__global__ void gates_gemm(const float* __restrict__ r0, const float* __restrict__ Wih,
                           const float* __restrict__ c, float* __restrict__ gates) {
    constexpr int RT = 32;
    int ct = blockIdx.x, rt = blockIdx.y, k = blockIdx.z;
    __shared__ __align__(16) float sR[RT * 256];
    int tid = threadIdx.x;
    const float* rbase = r0 + ((size_t)k * P_PATH + rt * RT) * 256;
    for (int i = tid; i < RT * 256; i += 256) sR[i] = rbase[i];
    __syncthreads();
    int j = ct * 256 + tid;
    const float* wrow = Wih + ((size_t)k * 1024 + j) * 512 + 256;
    float acc[RT];
#pragma unroll
    for (int r = 0; r < RT; r++) acc[r] = 0.f;
    for (int d = 0; d < 256; d += 4) {
        float4 w4 = *reinterpret_cast<const float4*>(wrow + d);
#pragma unroll
        for (int r = 0; r < RT; r++) {
            float4 s4 = *reinterpret_cast<const float4*>(&sR[r * 256 + d]);
            acc[r] += s4.x * w4.x + s4.y * w4.y + s4.z * w4.z + s4.w * w4.w;
        }
    }
    float cj = c[k * 1024 + j];
#pragma unroll
    for (int r = 0; r < RT; r++)
        gates[((size_t)k * P_PATH + rt * RT + r) * 1024 + j] = acc[r] + cj;
}

// ---------------- iter-1 LSTM elementwise -> q1 ----------------
__global__ void lstm_kernel(const float* __restrict__ gates, const float* __restrict__ cs0,
                            float* __restrict__ q1) {
    int idx = blockIdx.x * blockDim.x + threadIdx.x;
    if (idx >= 3 * P_PATH * 256) return;
    int d = idx & 255;
    int pk = idx >> 8;
    int k = pk >> 9;
    const float* g = gates + (size_t)pk * 1024;
    float gi = g[d], gf = g[256 + d], gg = g[512 + d], go = g[768 + d];
    float cs = sigm(gf) * cs0[k * 256 + d] + sigm(gi) * tanhf(gg);
    q1[idx] = sigm(go) * tanhf(cs);
}

// ---------------- xg[p] = bg + sum_k (q1_k . Wg_q + r1_k . Wg_r) ----------------
__global__ void xg_kernel(const float* __restrict__ q1, const float* __restrict__ r1,
                          const float* __restrict__ Wg, const float* __restrict__ bg,
                          float* __restrict__ xg) {
    int p = blockIdx.x, tid = threadIdx.x;
    float acc = 0.f;
#pragma unroll
    for (int k = 0; k < 3; k++) {
        acc += q1[((size_t)k * P_PATH + p) * 256 + tid] * Wg[k * 512 + tid];
        acc += r1[((size_t)k * P_PATH + p) * 256 + tid] * Wg[k * 512 + 256 + tid];
    }
    __shared__ float sred[8];
    for (int off = 16; off; off >>= 1) acc += __shfl_xor_sync(0xffffffffu, acc, off);
    if ((tid & 31) == 0) sred[tid >> 5] = acc;
    __syncthreads();
    if (tid == 0) {
        float t = 0.f;
#pragma unroll
        for (int i = 0; i < 8; i++) t += sred[i];
        xg[p] = t + bg[0];
    }
}

// ---------------- final MLP: [1,512] -> tanh 256 -> relu 64 -> sigmoid 1 ----------------
__global__ void final_kernel(const float* __restrict__ xg, const float* __restrict__ Wl1,
                             const float* __restrict__ bl1, const float* __restrict__ Wl2,
                             const float* __restrict__ bl2, const float* __restrict__ Wl3,
                             const float* __restrict__ bl3, float* __restrict__ out) {
    __shared__ __align__(16) float sxg[512];
    __shared__ __align__(16) float sz1[256];
    __shared__ float sz2[64];
    int tid = threadIdx.x;
    sxg[tid] = xg[tid];
    sxg[tid + 256] = xg[tid + 256];
    __syncthreads();
    {
        float a = bl1[tid];
        const float* w = Wl1 + (size_t)tid * 512;
        for (int p = 0; p < 512; p += 4) {
            float4 w4 = *reinterpret_cast<const float4*>(w + p);
            float4 x4 = *reinterpret_cast<const float4*>(&sxg[p]);
            a += w4.x * x4.x + w4.y * x4.y + w4.z * x4.z + w4.w * x4.w;
        }
        sz1[tid] = tanhf(a);
    }
    __syncthreads();
    if (tid < 64) {
        float bacc = bl2[tid];
        const float* w2 = Wl2 + (size_t)tid * 256;
        for (int hh = 0; hh < 256; hh += 4) {
            float4 w4 = *reinterpret_cast<const float4*>(w2 + hh);
            float4 z4 = *reinterpret_cast<const float4*>(&sz1[hh]);
            bacc += w4.x * z4.x + w4.y * z4.y + w4.z * z4.z + w4.w * z4.w;
        }
        sz2[tid] = fmaxf(bacc, 0.f);
    }
    __syncthreads();
    if (tid == 0) {
        float cacc = bl3[0];
        for (int j = 0; j < 64; j++) cacc += sz2[j] * Wl3[j];
        out[0] = 1.f / (1.f + __expf(-cacc));
    }
}

// ---------------- host launcher ----------------
extern "C" void kernel_launch(void* const* d_in, const int* in_sizes, int n_in,
                              void* d_out, int out_size) {
    const float* h = (const float*)d_in[0];
    const int* src = (const int*)d_in[1];
    const int* dst = (const int*)d_in[2];
    const int* pn = (const int*)d_in[3];
    const float* W1 = (const float*)d_in[4];
    const float* b1 = (const float*)d_in[5];
    const float* W2 = (const float*)d_in[6];
    const float* b2 = (const float*)d_in[7];
    const float* W3 = (const float*)d_in[8];
    const float* b3 = (const float*)d_in[9];
    const float* W4 = (const float*)d_in[10];
    const float* b4 = (const float*)d_in[11];
    const float* Wih = (const float*)d_in[12];
    const float* Whh = (const float*)d_in[13];
    const float* bih = (const float*)d_in[14];
    const float* bhh = (const float*)d_in[15];
    const float* Wg = (const float*)d_in[16];
    const float* bg = (const float*)d_in[17];
    const float* Wl1 = (const float*)d_in[18];
    const float* bl1 = (const float*)d_in[19];
    const float* Wl2 = (const float*)d_in[20];
    const float* bl2 = (const float*)d_in[21];
    const float* Wl3 = (const float*)d_in[22];
    const float* bl3 = (const float*)d_in[23];
    int E = in_sizes[1];
    float* out = (float*)d_out;

    float *agg, *part, *h1, *h2, *h3, *h4, *q0, *cs0, *cvec, *r0, *gates, *q1, *r1, *xg;
    int *deg, *off, *cur, *srcs;
    cudaGetSymbolAddress((void**)&agg, g_agg);
    cudaGetSymbolAddress((void**)&part, g_part);
    cudaGetSymbolAddress((void**)&h1, g_h1);
    cudaGetSymbolAddress((void**)&h2, g_h2);
    cudaGetSymbolAddress((void**)&h3, g_h3);
    cudaGetSymbolAddress((void**)&h4, g_h4);
    cudaGetSymbolAddress((void**)&q0, g_q0);
    cudaGetSymbolAddress((void**)&cs0, g_cs0);
    cudaGetSymbolAddress((void**)&cvec, g_c);
    cudaGetSymbolAddress((void**)&r0, g_r0);
    cudaGetSymbolAddress((void**)&gates, g_gates);
    cudaGetSymbolAddress((void**)&q1, g_q1);
    cudaGetSymbolAddress((void**)&r1, g_r1);
    cudaGetSymbolAddress((void**)&xg, g_xg);
    cudaGetSymbolAddress((void**)&deg, g_deg);
    cudaGetSymbolAddress((void**)&off, g_off);
    cudaGetSymbolAddress((void**)&cur, g_cur);
    cudaGetSymbolAddress((void**)&srcs, g_srcs);

    // smem sizes for gemm_relu<K,N,NP,T,RPB>: (N*(K+4) + RPB*K) * 4 bytes
    const int smem1 = (24 * 12 + 32 * 8) * 4;
    const int smem2 = (64 * 28 + 32 * 24) * 4;
    const int smem3 = (128 * 68 + 64 * 64) * 4;    // 51.2 KB
    const int smem4 = (256 * 132 + 64 * 128) * 4;  // ~168 KB
    cudaFuncSetAttribute(gemm_relu<64, 128, 128, 512, 64>,
                         cudaFuncAttributeMaxDynamicSharedMemorySize, smem3);
    cudaFuncSetAttribute(gemm_relu<128, 256, 256, 512, 64>,
                         cudaFuncAttributeMaxDynamicSharedMemorySize, smem4);
    const int attn_smem = (64 * 256 + 256 + 64 + 64) * 4;  // ~66.9 KB
    cudaFuncSetAttribute(attn_kernel, cudaFuncAttributeMaxDynamicSharedMemorySize, attn_smem);

    // ---- CSR build (once; reused by all 4 layers) ----
    cudaMemsetAsync(deg, 0, NN * sizeof(int));
    hist_kernel<<<(E + 255) / 256, 256>>>(dst, deg, E);
    scan_kernel<<<1, 1024>>>(deg, off, cur);
    bucket_kernel<<<(E + 255) / 256, 256>>>(src, dst, cur, srcs, E);

    // ---- 4 GIN layers ----
    // layer 1: D=8 sliced (NS=8)
    aggregate_sliced<8, 8><<<(NN * 2 * 8 + 255) / 256, 256>>>(h, off, srcs, part);
    combine_k<8, 8><<<(NN * 2 + 255) / 256, 256>>>(h, part, agg);
    gemm_relu<8, 24, 32, 256, 32><<<(NN + 31) / 32, 256, smem1>>>(agg, W1, b1, h1, NN);

    // layer 2: D=24 sliced (NS=4)
    aggregate_sliced<24, 4><<<(NN * 6 * 4 + 255) / 256, 256>>>(h1, off, srcs, part);
    combine_k<24, 4><<<(NN * 6 + 255) / 256, 256>>>(h1, part, agg);
    gemm_relu<24, 64, 64, 256, 32><<<(NN + 31) / 32, 256, smem2>>>(agg, W2, b2, h2, NN);

    // layer 3: D=64 direct
    aggregate_k<64><<<(NN * 16 + 255) / 256, 256>>>(h2, off, srcs, agg);
    gemm_relu<64, 128, 128, 512, 64><<<(NN + 63) / 64, 512, smem3>>>(agg, W3, b3, h3, NN);

    // layer 4: D=128 direct
    aggregate_k<128><<<(NN * 32 + 255) / 256, 256>>>(h3, off, srcs, agg);
    gemm_relu<128, 256, 256, 512, 64><<<(NN + 63) / 64, 512, smem4>>>(agg, W4, b4, h4, NN);

    // ---- Set2Set (3 modules batched via grid dims; gather fused into attention) ----
    s2s_init<<<3, 256>>>(bih, bhh, cs0, q0);
    attn_kernel<<<dim3(P_PATH, 3), 256, attn_smem>>>(h4, pn, q0, 0, r0);
    s2s_cvec<<<dim3(4, 3), 256>>>(Wih, Whh, bih, bhh, q0, cvec);
    gates_gemm<<<dim3(4, P_PATH / 32, 3), 256>>>(r0, Wih, cvec, gates);
    lstm_kernel<<<(3 * P_PATH * 256 + 255) / 256, 256>>>(gates, cs0, q1);
    attn_kernel<<<dim3(P_PATH, 3), 256, attn_smem>>>(h4, pn, q1, 1, r1);

    xg_kernel<<<P_PATH, 256>>>(q1, r1, Wg, bg, xg);
    final_kernel<<<1, 256>>>(xg, Wl1, bl1, Wl2, bl2, Wl3, bl3, out);
}